// round 6
// baseline (speedup 1.0000x reference)
#include <cuda_runtime.h>
#include <cuda_bf16.h>
#include <cstdint>

#define GRID_BLOCKS 148
#define THREADS     512
#define NSTAGES     6
#define CHUNK       4096                    // floats per array per stage
#define STAGE_ARR_BYTES (CHUNK * 4)         // 16384
#define STAGE_BYTES     (2 * STAGE_ARR_BYTES)
#define SMEM_DATA_OFF   1024
#define SMEM_TOTAL      (SMEM_DATA_OFF + NSTAGES * STAGE_BYTES)

__device__ float g_partials[GRID_BLOCKS];
__device__ unsigned int g_ticket;           // zero-init; atomicInc wraps to 0

__device__ __forceinline__ uint32_t smem_u32(const void* p) {
    uint32_t a;
    asm("{ .reg .u64 t; cvta.to.shared.u64 t, %1; cvt.u32.u64 %0, t; }"
        : "=r"(a) : "l"(p));
    return a;
}
__device__ __forceinline__ void mbar_init(uint32_t bar, uint32_t cnt) {
    asm volatile("mbarrier.init.shared.b64 [%0], %1;" :: "r"(bar), "r"(cnt) : "memory");
}
__device__ __forceinline__ void mbar_expect_tx(uint32_t bar, uint32_t bytes) {
    asm volatile("mbarrier.arrive.expect_tx.shared.b64 _, [%0], %1;"
                 :: "r"(bar), "r"(bytes) : "memory");
}
__device__ __forceinline__ void mbar_arrive(uint32_t bar) {
    asm volatile("mbarrier.arrive.shared.b64 _, [%0];" :: "r"(bar) : "memory");
}
__device__ __forceinline__ void mbar_wait(uint32_t bar, uint32_t parity) {
    asm volatile(
        "{\n\t"
        ".reg .pred P;\n\t"
        "WL_%=:\n\t"
        "mbarrier.try_wait.parity.shared.b64 P, [%0], %1, 0x989680;\n\t"
        "@P bra.uni WD_%=;\n\t"
        "bra.uni WL_%=;\n\t"
        "WD_%=:\n\t"
        "}" :: "r"(bar), "r"(parity) : "memory");
}
__device__ __forceinline__ void bulk_ld(uint32_t dst, const void* src,
                                        uint32_t bytes, uint32_t bar) {
    asm volatile(
        "cp.async.bulk.shared::cta.global.mbarrier::complete_tx::bytes "
        "[%0], [%1], %2, [%3];"
        :: "r"(dst), "l"(src), "r"(bytes), "r"(bar) : "memory");
}

__global__ void __launch_bounds__(THREADS, 1)
qsum_tma_kernel(const float* __restrict__ phi,
                const float* __restrict__ w,
                int n, int nchunks,
                float add_const, float inv_m,
                float* __restrict__ out)
{
    extern __shared__ char smem[];
    const uint32_t sbase = smem_u32(smem);
    const int tid = threadIdx.x;
    const int bid = blockIdx.x;
    const int grid = gridDim.x;

    // interleaved barrier ring: full[s] at s*16, empty[s] at s*16+8
    if (tid == 0) {
        #pragma unroll
        for (int s = 0; s < NSTAGES; s++) {
            mbar_init(sbase + s * 16,     1);        // full: 1 expect_tx arrive
            mbar_init(sbase + s * 16 + 8, THREADS);  // empty: all threads
        }
    }
    __syncthreads();

    // chunks for this block: global chunk g = bid + i*grid
    int mine = (nchunks > bid) ? ((nchunks - 1 - bid) / grid + 1) : 0;

    float acc = 0.0f;

    // prologue: fill first min(NSTAGES, mine) stages
    if (tid == 0) {
        int pre = mine < NSTAGES ? mine : NSTAGES;
        for (int k = 0; k < pre; k++) {
            long long g = (long long)bid + (long long)k * grid;
            uint32_t full = sbase + (k % NSTAGES) * 16;
            uint32_t dst  = sbase + SMEM_DATA_OFF + (k % NSTAGES) * STAGE_BYTES;
            mbar_expect_tx(full, STAGE_BYTES);
            bulk_ld(dst,                  phi + g * CHUNK, STAGE_ARR_BYTES, full);
            bulk_ld(dst + STAGE_ARR_BYTES, w  + g * CHUNK, STAGE_ARR_BYTES, full);
        }
    }

    for (int i = 0; i < mine; i++) {
        int s = i % NSTAGES;
        int j = i / NSTAGES;
        uint32_t full  = sbase + s * 16;
        uint32_t empty = sbase + s * 16 + 8;

        mbar_wait(full, (uint32_t)(j & 1));

        const float4* sp = reinterpret_cast<const float4*>(
            smem + SMEM_DATA_OFF + s * STAGE_BYTES);
        const float4* sq = reinterpret_cast<const float4*>(
            smem + SMEM_DATA_OFF + s * STAGE_BYTES + STAGE_ARR_BYTES);

        #pragma unroll
        for (int r = 0; r < CHUNK / 4 / THREADS; r++) {   // 2 float4 per array
            float4 p = sp[tid + r * THREADS];
            float4 q = sq[tid + r * THREADS];
            acc += __cosf(p.x * q.x);
            acc += __cosf(p.y * q.y);
            acc += __cosf(p.z * q.z);
            acc += __cosf(p.w * q.w);
        }

        mbar_arrive(empty);

        if (tid == 0 && i + NSTAGES < mine) {
            // refill this stage for fill j+1 once consumption j drains
            mbar_wait(empty, (uint32_t)(j & 1));
            long long g = (long long)bid + (long long)(i + NSTAGES) * grid;
            uint32_t dst = sbase + SMEM_DATA_OFF + s * STAGE_BYTES;
            mbar_expect_tx(full, STAGE_BYTES);
            bulk_ld(dst,                  phi + g * CHUNK, STAGE_ARR_BYTES, full);
            bulk_ld(dst + STAGE_ARR_BYTES, w  + g * CHUNK, STAGE_ARR_BYTES, full);
        }
    }

    // tail elements beyond nchunks*CHUNK (zero for n = 2^24): block 0, plain LDG
    long long done = (long long)nchunks * CHUNK;
    if (bid == 0) {
        for (long long idx = done + tid; idx < (long long)n; idx += THREADS)
            acc += __cosf(phi[idx] * w[idx]);
    }

    // block reduce (512 threads, 16 warps)
    #pragma unroll
    for (int off = 16; off > 0; off >>= 1)
        acc += __shfl_down_sync(0xFFFFFFFFu, acc, off);

    __shared__ float s_warp[THREADS / 32];
    int lane = tid & 31;
    int wid  = tid >> 5;
    if (lane == 0) s_warp[wid] = acc;
    __syncthreads();

    __shared__ bool s_last;
    if (tid == 0) {
        float v = 0.0f;
        #pragma unroll
        for (int k = 0; k < THREADS / 32; k++) v += s_warp[k];
        g_partials[bid] = v;
        __threadfence();
        unsigned int t = atomicInc(&g_ticket, (unsigned int)(gridDim.x - 1));
        s_last = (t == (unsigned int)(gridDim.x - 1));
    }
    __syncthreads();

    if (s_last) {
        // deterministic fixed-order reduce of 148 partials (warp 0 only)
        if (wid == 0) {
            double v = 0.0;
            for (int k = lane; k < (int)gridDim.x; k += 32)
                v += (double)g_partials[k];
            #pragma unroll
            for (int off = 16; off > 0; off >>= 1)
                v += __shfl_down_sync(0xFFFFFFFFu, v, off);
            if (lane == 0)
                out[0] = (float)((v + (double)add_const) * (double)inv_m);
        }
    }
}

extern "C" void kernel_launch(void* const* d_in, const int* in_sizes, int n_in,
                              void* d_out, int out_size)
{
    const float* phi = (const float*)d_in[0];
    const float* w   = (const float*)d_in[1];
    float* out = (float*)d_out;
    int n = in_sizes[0];

    long long M = 1;
    while (M < (long long)n) M <<= 1;
    float add_const = (float)(M - (long long)n);
    float inv_m = (float)(1.0 / (double)M);

    int nchunks = n / CHUNK;

    static int smem_set = 0;
    if (!smem_set) {
        cudaFuncSetAttribute(qsum_tma_kernel,
                             cudaFuncAttributeMaxDynamicSharedMemorySize,
                             SMEM_TOTAL);
        smem_set = 1;
    }

    qsum_tma_kernel<<<GRID_BLOCKS, THREADS, SMEM_TOTAL>>>(
        phi, w, n, nchunks, add_const, inv_m, out);
}